// round 3
// baseline (speedup 1.0000x reference)
#include <cuda_runtime.h>
#include <cuda_bf16.h>

// Problem constants (match reference)
#define NN   100000      // nodes
#define FIN  128         // input features
#define HID  64          // hidden
#define NCLS 40          // classes
#define NE   1600000     // edges

// Scratch (device globals — no allocation allowed)
__device__ int   g_is64;
__device__ float g_deg [NN];
__device__ float g_dinv[NN];
__device__ float g_hs1 [NN * HID];   // (x@W1)*dinv[row]
__device__ float g_acc1[NN * HID];   // hs1 + sum of neighbor hs1
__device__ float g_hs2 [NN * NCLS];  // (relu(l1)@W2)*dinv[row]

// ---------------------------------------------------------------------------
// Detect edge-index dtype at runtime (JAX may silently emit int32 even though
// the reference asks for int64). If ANY 8-byte word in the prefix is >= NN,
// the buffer cannot be int64 node indices -> it's int32.
__global__ void k_detect(const void* __restrict__ ei) {
    if (threadIdx.x == 0 && blockIdx.x == 0) {
        const unsigned long long* p = (const unsigned long long*)ei;
        int is64 = 1;
        for (int i = 0; i < 2048; i++) {
            if (p[i] >= (unsigned long long)NN) { is64 = 0; break; }
        }
        g_is64 = is64;
    }
}

__device__ __forceinline__ int edge_src(const void* __restrict__ ei, int e) {
    if (g_is64) return (int)((const long long*)ei)[e];
    return ((const int*)ei)[e];
}
__device__ __forceinline__ int edge_dst(const void* __restrict__ ei, int e) {
    if (g_is64) return (int)((const long long*)ei)[NE + e];
    return ((const int*)ei)[NE + e];
}

// ---------------------------------------------------------------------------
__global__ void k_zero_deg() {
    int i = blockIdx.x * blockDim.x + threadIdx.x;
    if (i < NN) g_deg[i] = 0.0f;
}

__global__ void k_deg(const void* __restrict__ ei) {
    int e = blockIdx.x * blockDim.x + threadIdx.x;
    if (e < NE) atomicAdd(&g_deg[edge_dst(ei, e)], 1.0f);
}

__global__ void k_dinv() {
    int i = blockIdx.x * blockDim.x + threadIdx.x;
    if (i < NN) g_dinv[i] = rsqrtf(g_deg[i] + 1.0f);
}

// ---------------------------------------------------------------------------
// GEMM1: hs1 = (x @ W1) * dinv[row];  acc1 = hs1 (self-loop init).
// One thread per row, full 64-col accumulator in registers, W1 in smem.
__global__ void k_gemm1(const float* __restrict__ x, const float* __restrict__ W1) {
    __shared__ float4 Ws[FIN * HID / 4];  // 2048 float4 = 32KB
    for (int i = threadIdx.x; i < FIN * HID / 4; i += blockDim.x)
        Ws[i] = ((const float4*)W1)[i];
    __syncthreads();

    int row = blockIdx.x * blockDim.x + threadIdx.x;
    if (row >= NN) return;

    float acc[HID];
#pragma unroll
    for (int c = 0; c < HID; c++) acc[c] = 0.0f;

    const float4* xr = (const float4*)(x + (size_t)row * FIN);
#pragma unroll 4
    for (int k4 = 0; k4 < FIN / 4; k4++) {
        float4 xv = __ldg(xr + k4);
        float xk[4] = {xv.x, xv.y, xv.z, xv.w};
#pragma unroll
        for (int kk = 0; kk < 4; kk++) {
            const float4* wr = &Ws[(k4 * 4 + kk) * (HID / 4)];
            float xs = xk[kk];
#pragma unroll
            for (int c4 = 0; c4 < HID / 4; c4++) {
                float4 w = wr[c4];
                acc[c4 * 4 + 0] += xs * w.x;
                acc[c4 * 4 + 1] += xs * w.y;
                acc[c4 * 4 + 2] += xs * w.z;
                acc[c4 * 4 + 3] += xs * w.w;
            }
        }
    }

    float di = g_dinv[row];
    float4* h1 = (float4*)(g_hs1  + (size_t)row * HID);
    float4* a1 = (float4*)(g_acc1 + (size_t)row * HID);
#pragma unroll
    for (int c4 = 0; c4 < HID / 4; c4++) {
        float4 v = make_float4(acc[c4 * 4 + 0] * di, acc[c4 * 4 + 1] * di,
                               acc[c4 * 4 + 2] * di, acc[c4 * 4 + 3] * di);
        h1[c4] = v;
        a1[c4] = v;
    }
}

// ---------------------------------------------------------------------------
// Scatter layer 1: acc1[dst] += hs1[src]  (16 float4 per edge, vector RED)
__global__ void k_scatter1(const void* __restrict__ ei) {
    int idx = blockIdx.x * blockDim.x + threadIdx.x;  // NE*16 threads
    int e = idx >> 4, g = idx & 15;
    if (e >= NE) return;
    int s = edge_src(ei, e);
    int d = edge_dst(ei, e);
    float4 v = ((const float4*)g_hs1)[s * 16 + g];
    atomicAdd(((float4*)g_acc1) + d * 16 + g, v);
}

// ---------------------------------------------------------------------------
// GEMM2: in = relu(acc1[row]*dinv[row] + b1); hs2 = (in@W2)*dinv[row];
// also initializes out = hs2 (self-loop term for layer 2).
__global__ void k_gemm2(const float* __restrict__ W2, const float* __restrict__ b1,
                        float* __restrict__ out) {
    __shared__ float4 Ws[HID * NCLS / 4];  // 640 float4 = 10KB
    __shared__ float  b1s[HID];
    for (int i = threadIdx.x; i < HID * NCLS / 4; i += blockDim.x)
        Ws[i] = ((const float4*)W2)[i];
    for (int i = threadIdx.x; i < HID; i += blockDim.x) b1s[i] = b1[i];
    __syncthreads();

    int row = blockIdx.x * blockDim.x + threadIdx.x;
    if (row >= NN) return;

    float di = g_dinv[row];
    float acc[NCLS];
#pragma unroll
    for (int c = 0; c < NCLS; c++) acc[c] = 0.0f;

    const float4* ar = (const float4*)(g_acc1 + (size_t)row * HID);
#pragma unroll 4
    for (int k4 = 0; k4 < HID / 4; k4++) {
        float4 av = ar[k4];
        float ak[4] = {av.x, av.y, av.z, av.w};
#pragma unroll
        for (int kk = 0; kk < 4; kk++) {
            int k = k4 * 4 + kk;
            float xv = fmaxf(ak[kk] * di + b1s[k], 0.0f);  // relu(l1 out)
            const float4* wr = &Ws[k * (NCLS / 4)];
#pragma unroll
            for (int c4 = 0; c4 < NCLS / 4; c4++) {
                float4 w = wr[c4];
                acc[c4 * 4 + 0] += xv * w.x;
                acc[c4 * 4 + 1] += xv * w.y;
                acc[c4 * 4 + 2] += xv * w.z;
                acc[c4 * 4 + 3] += xv * w.w;
            }
        }
    }

    float4* h2 = (float4*)(g_hs2 + (size_t)row * NCLS);
    float4* o  = (float4*)(out   + (size_t)row * NCLS);
#pragma unroll
    for (int c4 = 0; c4 < NCLS / 4; c4++) {
        float4 v = make_float4(acc[c4 * 4 + 0] * di, acc[c4 * 4 + 1] * di,
                               acc[c4 * 4 + 2] * di, acc[c4 * 4 + 3] * di);
        h2[c4] = v;
        o[c4]  = v;
    }
}

// ---------------------------------------------------------------------------
// Scatter layer 2: out[dst] += hs2[src]  (10 float4 per edge)
__global__ void k_scatter2(const void* __restrict__ ei, float* __restrict__ out) {
    int idx = blockIdx.x * blockDim.x + threadIdx.x;  // NE*10 threads
    int e = idx / 10, g = idx % 10;
    if (e >= NE) return;
    int s = edge_src(ei, e);
    int d = edge_dst(ei, e);
    float4 v = ((const float4*)g_hs2)[s * 10 + g];
    atomicAdd(((float4*)out) + d * 10 + g, v);
}

// ---------------------------------------------------------------------------
// Final: out = out * dinv[node] + b2  (in place, vectorized over float4)
__global__ void k_final(const float* __restrict__ b2, float* __restrict__ out) {
    int idx = blockIdx.x * blockDim.x + threadIdx.x;  // NN*10
    if (idx >= NN * 10) return;
    int node = idx / 10, g = idx % 10;
    float di = g_dinv[node];
    float4 bv = __ldg(((const float4*)b2) + g);
    float4* o = ((float4*)out) + idx;
    float4 v = *o;
    v.x = v.x * di + bv.x;
    v.y = v.y * di + bv.y;
    v.z = v.z * di + bv.z;
    v.w = v.w * di + bv.w;
    *o = v;
}

// ---------------------------------------------------------------------------
extern "C" void kernel_launch(void* const* d_in, const int* in_sizes, int n_in,
                              void* d_out, int out_size) {
    const float* x   = (const float*)d_in[0];
    const void*  ei  = d_in[1];                 // [2, NE], int32 OR int64
    const float* W1  = (const float*)d_in[2];
    const float* b1  = (const float*)d_in[3];
    const float* W2  = (const float*)d_in[4];
    const float* b2  = (const float*)d_in[5];
    float*       out = (float*)d_out;

    // dtype detection + degree + dinv
    k_detect<<<1, 32>>>(ei);
    k_zero_deg<<<(NN + 255) / 256, 256>>>();
    k_deg<<<(NE + 255) / 256, 256>>>(ei);
    k_dinv<<<(NN + 255) / 256, 256>>>();

    // layer 1
    k_gemm1<<<(NN + 127) / 128, 128>>>(x, W1);
    k_scatter1<<<(NE * 16) / 256, 256>>>(ei);

    // layer 2 (fuses relu(l1*dinv+b1) into GEMM2 input)
    k_gemm2<<<(NN + 127) / 128, 128>>>(W2, b1, out);
    k_scatter2<<<(NE * 10 + 319) / 320, 320>>>(ei, out);

    // epilogue: out = out*dinv + b2
    k_final<<<(NN * 10 + 255) / 256, 256>>>(b2, out);
}

// round 4
// speedup vs baseline: 1.0074x; 1.0074x over previous
#include <cuda_runtime.h>
#include <cuda_bf16.h>

// Problem constants (match reference)
#define NN   100000      // nodes
#define FIN  128         // input features
#define HID  64          // hidden
#define NCLS 40          // classes
#define NE   1600000     // edges

// Scratch (device globals — no allocation allowed)
__device__ int   g_is64;
__device__ float g_deg [NN];
__device__ float g_dinv[NN];
__device__ float g_hs1 [NN * HID];   // (x@W1)*dinv[row]
__device__ float g_acc1[NN * HID];   // hs1 + sum of neighbor hs1
__device__ float g_hs2 [NN * NCLS];  // (relu(l1)@W2)*dinv[row]

// ---------------------------------------------------------------------------
// Detect edge-index dtype at runtime (JAX may silently emit int32 even though
// the reference asks for int64). If ANY 8-byte word in the prefix is >= NN,
// the buffer cannot be int64 node indices -> it's int32.
__global__ void k_detect(const void* __restrict__ ei) {
    if (threadIdx.x == 0 && blockIdx.x == 0) {
        const unsigned long long* p = (const unsigned long long*)ei;
        int is64 = 1;
        for (int i = 0; i < 2048; i++) {
            if (p[i] >= (unsigned long long)NN) { is64 = 0; break; }
        }
        g_is64 = is64;
    }
}

__device__ __forceinline__ int edge_src(const void* __restrict__ ei, int e) {
    if (g_is64) return (int)((const long long*)ei)[e];
    return ((const int*)ei)[e];
}
__device__ __forceinline__ int edge_dst(const void* __restrict__ ei, int e) {
    if (g_is64) return (int)((const long long*)ei)[NE + e];
    return ((const int*)ei)[NE + e];
}

// ---------------------------------------------------------------------------
__global__ void k_zero_deg() {
    int i = blockIdx.x * blockDim.x + threadIdx.x;
    if (i < NN) g_deg[i] = 0.0f;
}

__global__ void k_deg(const void* __restrict__ ei) {
    int e = blockIdx.x * blockDim.x + threadIdx.x;
    if (e < NE) atomicAdd(&g_deg[edge_dst(ei, e)], 1.0f);
}

__global__ void k_dinv() {
    int i = blockIdx.x * blockDim.x + threadIdx.x;
    if (i < NN) g_dinv[i] = rsqrtf(g_deg[i] + 1.0f);
}

// ---------------------------------------------------------------------------
// GEMM1: hs1 = (x @ W1) * dinv[row];  acc1 = hs1 (self-loop init).
// One thread per row, full 64-col accumulator in registers, W1 in smem.
__global__ void k_gemm1(const float* __restrict__ x, const float* __restrict__ W1) {
    __shared__ float4 Ws[FIN * HID / 4];  // 2048 float4 = 32KB
    for (int i = threadIdx.x; i < FIN * HID / 4; i += blockDim.x)
        Ws[i] = ((const float4*)W1)[i];
    __syncthreads();

    int row = blockIdx.x * blockDim.x + threadIdx.x;
    if (row >= NN) return;

    float acc[HID];
#pragma unroll
    for (int c = 0; c < HID; c++) acc[c] = 0.0f;

    const float4* xr = (const float4*)(x + (size_t)row * FIN);
#pragma unroll 4
    for (int k4 = 0; k4 < FIN / 4; k4++) {
        float4 xv = __ldg(xr + k4);
        float xk[4] = {xv.x, xv.y, xv.z, xv.w};
#pragma unroll
        for (int kk = 0; kk < 4; kk++) {
            const float4* wr = &Ws[(k4 * 4 + kk) * (HID / 4)];
            float xs = xk[kk];
#pragma unroll
            for (int c4 = 0; c4 < HID / 4; c4++) {
                float4 w = wr[c4];
                acc[c4 * 4 + 0] += xs * w.x;
                acc[c4 * 4 + 1] += xs * w.y;
                acc[c4 * 4 + 2] += xs * w.z;
                acc[c4 * 4 + 3] += xs * w.w;
            }
        }
    }

    float di = g_dinv[row];
    float4* h1 = (float4*)(g_hs1  + (size_t)row * HID);
    float4* a1 = (float4*)(g_acc1 + (size_t)row * HID);
#pragma unroll
    for (int c4 = 0; c4 < HID / 4; c4++) {
        float4 v = make_float4(acc[c4 * 4 + 0] * di, acc[c4 * 4 + 1] * di,
                               acc[c4 * 4 + 2] * di, acc[c4 * 4 + 3] * di);
        h1[c4] = v;
        a1[c4] = v;
    }
}

// ---------------------------------------------------------------------------
// Scatter layer 1: acc1[dst] += hs1[src]  (16 float4 per edge, vector RED)
__global__ void k_scatter1(const void* __restrict__ ei) {
    int idx = blockIdx.x * blockDim.x + threadIdx.x;  // NE*16 threads
    int e = idx >> 4, g = idx & 15;
    if (e >= NE) return;
    int s = edge_src(ei, e);
    int d = edge_dst(ei, e);
    float4 v = ((const float4*)g_hs1)[s * 16 + g];
    atomicAdd(((float4*)g_acc1) + d * 16 + g, v);
}

// ---------------------------------------------------------------------------
// GEMM2: in = relu(acc1[row]*dinv[row] + b1); hs2 = (in@W2)*dinv[row];
// also initializes out = hs2 (self-loop term for layer 2).
__global__ void k_gemm2(const float* __restrict__ W2, const float* __restrict__ b1,
                        float* __restrict__ out) {
    __shared__ float4 Ws[HID * NCLS / 4];  // 640 float4 = 10KB
    __shared__ float  b1s[HID];
    for (int i = threadIdx.x; i < HID * NCLS / 4; i += blockDim.x)
        Ws[i] = ((const float4*)W2)[i];
    for (int i = threadIdx.x; i < HID; i += blockDim.x) b1s[i] = b1[i];
    __syncthreads();

    int row = blockIdx.x * blockDim.x + threadIdx.x;
    if (row >= NN) return;

    float di = g_dinv[row];
    float acc[NCLS];
#pragma unroll
    for (int c = 0; c < NCLS; c++) acc[c] = 0.0f;

    const float4* ar = (const float4*)(g_acc1 + (size_t)row * HID);
#pragma unroll 4
    for (int k4 = 0; k4 < HID / 4; k4++) {
        float4 av = ar[k4];
        float ak[4] = {av.x, av.y, av.z, av.w};
#pragma unroll
        for (int kk = 0; kk < 4; kk++) {
            int k = k4 * 4 + kk;
            float xv = fmaxf(ak[kk] * di + b1s[k], 0.0f);  // relu(l1 out)
            const float4* wr = &Ws[k * (NCLS / 4)];
#pragma unroll
            for (int c4 = 0; c4 < NCLS / 4; c4++) {
                float4 w = wr[c4];
                acc[c4 * 4 + 0] += xv * w.x;
                acc[c4 * 4 + 1] += xv * w.y;
                acc[c4 * 4 + 2] += xv * w.z;
                acc[c4 * 4 + 3] += xv * w.w;
            }
        }
    }

    float4* h2 = (float4*)(g_hs2 + (size_t)row * NCLS);
    float4* o  = (float4*)(out   + (size_t)row * NCLS);
#pragma unroll
    for (int c4 = 0; c4 < NCLS / 4; c4++) {
        float4 v = make_float4(acc[c4 * 4 + 0] * di, acc[c4 * 4 + 1] * di,
                               acc[c4 * 4 + 2] * di, acc[c4 * 4 + 3] * di);
        h2[c4] = v;
        o[c4]  = v;
    }
}

// ---------------------------------------------------------------------------
// Scatter layer 2: out[dst] += hs2[src]  (10 float4 per edge)
__global__ void k_scatter2(const void* __restrict__ ei, float* __restrict__ out) {
    int idx = blockIdx.x * blockDim.x + threadIdx.x;  // NE*10 threads
    int e = idx / 10, g = idx % 10;
    if (e >= NE) return;
    int s = edge_src(ei, e);
    int d = edge_dst(ei, e);
    float4 v = ((const float4*)g_hs2)[s * 10 + g];
    atomicAdd(((float4*)out) + d * 10 + g, v);
}

// ---------------------------------------------------------------------------
// Final: out = out * dinv[node] + b2  (in place, vectorized over float4)
__global__ void k_final(const float* __restrict__ b2, float* __restrict__ out) {
    int idx = blockIdx.x * blockDim.x + threadIdx.x;  // NN*10
    if (idx >= NN * 10) return;
    int node = idx / 10, g = idx % 10;
    float di = g_dinv[node];
    float4 bv = __ldg(((const float4*)b2) + g);
    float4* o = ((float4*)out) + idx;
    float4 v = *o;
    v.x = v.x * di + bv.x;
    v.y = v.y * di + bv.y;
    v.z = v.z * di + bv.z;
    v.w = v.w * di + bv.w;
    *o = v;
}

// ---------------------------------------------------------------------------
extern "C" void kernel_launch(void* const* d_in, const int* in_sizes, int n_in,
                              void* d_out, int out_size) {
    const float* x   = (const float*)d_in[0];
    const void*  ei  = d_in[1];                 // [2, NE], int32 OR int64
    const float* W1  = (const float*)d_in[2];
    const float* b1  = (const float*)d_in[3];
    const float* W2  = (const float*)d_in[4];
    const float* b2  = (const float*)d_in[5];
    float*       out = (float*)d_out;

    // dtype detection + degree + dinv
    k_detect<<<1, 32>>>(ei);
    k_zero_deg<<<(NN + 255) / 256, 256>>>();
    k_deg<<<(NE + 255) / 256, 256>>>(ei);
    k_dinv<<<(NN + 255) / 256, 256>>>();

    // layer 1
    k_gemm1<<<(NN + 127) / 128, 128>>>(x, W1);
    k_scatter1<<<(NE * 16) / 256, 256>>>(ei);

    // layer 2 (fuses relu(l1*dinv+b1) into GEMM2 input)
    k_gemm2<<<(NN + 127) / 128, 128>>>(W2, b1, out);
    k_scatter2<<<(NE * 10 + 319) / 320, 320>>>(ei, out);

    // epilogue: out = out*dinv + b2
    k_final<<<(NN * 10 + 255) / 256, 256>>>(b2, out);
}